// round 9
// baseline (speedup 1.0000x reference)
#include <cuda_runtime.h>
#include <cstdint>

#define B_ 32
#define I_ 1152
#define O_ 10
#define D_ 16
#define H_ 10
#define S_ 922
#define T_ 512
#define ROWSTRIDE (O_ * D_)   // 160 floats between consecutive i in u

__device__ __forceinline__ float sqrt_approx(float x) {
    float y;
    asm("sqrt.approx.f32 %0, %1;" : "=f"(y) : "f"(x));
    return y;
}

// ---------------------------------------------------------------------------
// One block per (b,o). u stays in L2 (23.6MB fits); smem holds only vn+mask
// (interleaved float2) + tiny reduction scratch => ~11KB/block => 3 blocks/SM
// capacity => the 320-block grid runs in ONE wave at ~75% occupancy.
//  0:  dtype probe; zero mask; vn via coalesced LDG + quad shfl; idx scatter
//  1:  masked weighted accumulation -> Mu numerators (5 acc/thread, u via LDG)
//  1b: den pass (10 warps); Mu = num/den; mu2
//  2:  quad-decomposed loss (2 passes x 5 h, Mu quarters in regs, u via LDG)
//  argmin by warp 0, emit Mu[h*]
// ---------------------------------------------------------------------------
__global__ void __launch_bounds__(T_, 3) fused_kernel(const float* __restrict__ u,
                                                      const int* __restrict__ idx,
                                                      float* __restrict__ out) {
    __shared__ __align__(8) float s_vm[2 * I_];    // [i]: (vn, mask bits)
    __shared__ float s_MuNum[H_ * D_];
    __shared__ float s_den[H_];
    __shared__ __align__(16) float s_Mu[H_][D_];
    __shared__ float s_mu2[H_];
    __shared__ float s_loss[16][H_];
    __shared__ int   s_is64;

    const int bo   = blockIdx.x;
    const int b    = bo / O_;
    const int o    = bo % O_;
    const int tid  = threadIdx.x;
    const int lane = tid & 31;
    const int w    = tid >> 5;      // warp 0..15

    const float* ub = u + ((size_t)b * I_ * O_ + o) * D_;

    // ---- phase 0: dtype probe + zero mask ----
    if (w == 0) {
        unsigned v = ((const unsigned*)idx)[2 * lane + 1]
                   | ((const unsigned*)idx)[2 * (lane + 32) + 1];
        unsigned r = __reduce_or_sync(0xffffffffu, v);
        if (lane == 0) s_is64 = (r == 0u) ? 1 : 0;
    }
    for (int j = tid; j < I_; j += T_) s_vm[2 * j + 1] = 0.f;
    if (tid < H_ * D_) s_MuNum[tid] = 0.f;
    __syncthreads();

    // ---- phase 0b: vn via coalesced LDG.128 + quad reduce; idx scatter ----
#pragma unroll 1
    for (int e = tid; e < I_ * 4; e += T_) {       // 9 iterations
        float4 q = *(const float4*)(ub + (size_t)(e >> 2) * ROWSTRIDE + (e & 3) * 4);
        float  p = q.x * q.x + q.y * q.y + q.z * q.z + q.w * q.w;
        p += __shfl_xor_sync(0xffffffffu, p, 1);
        p += __shfl_xor_sync(0xffffffffu, p, 2);
        if ((e & 3) == 0) s_vm[2 * (e >> 2)] = sqrt_approx(p);
    }

    if (s_is64) {
#pragma unroll 1
        for (int s = tid; s < S_; s += T_) {
            int base = ((b * S_ + s) * O_ + o) * H_;
            const int4* p = (const int4*)idx + (base >> 1);
            int4 a0 = p[0], a1 = p[1], a2 = p[2], a3 = p[3], a4 = p[4];
            atomicOr((unsigned*)&s_vm[2 * a0.x + 1], 1u << 0);
            atomicOr((unsigned*)&s_vm[2 * a0.z + 1], 1u << 1);
            atomicOr((unsigned*)&s_vm[2 * a1.x + 1], 1u << 2);
            atomicOr((unsigned*)&s_vm[2 * a1.z + 1], 1u << 3);
            atomicOr((unsigned*)&s_vm[2 * a2.x + 1], 1u << 4);
            atomicOr((unsigned*)&s_vm[2 * a2.z + 1], 1u << 5);
            atomicOr((unsigned*)&s_vm[2 * a3.x + 1], 1u << 6);
            atomicOr((unsigned*)&s_vm[2 * a3.z + 1], 1u << 7);
            atomicOr((unsigned*)&s_vm[2 * a4.x + 1], 1u << 8);
            atomicOr((unsigned*)&s_vm[2 * a4.z + 1], 1u << 9);
        }
    } else {
#pragma unroll 1
        for (int s = tid; s < S_; s += T_) {
            int base = ((b * S_ + s) * O_ + o) * H_;
            const int2* p = (const int2*)idx + (base >> 1);
            int2 a0 = p[0], a1 = p[1], a2 = p[2], a3 = p[3], a4 = p[4];
            atomicOr((unsigned*)&s_vm[2 * a0.x + 1], 1u << 0);
            atomicOr((unsigned*)&s_vm[2 * a0.y + 1], 1u << 1);
            atomicOr((unsigned*)&s_vm[2 * a1.x + 1], 1u << 2);
            atomicOr((unsigned*)&s_vm[2 * a1.y + 1], 1u << 3);
            atomicOr((unsigned*)&s_vm[2 * a2.x + 1], 1u << 4);
            atomicOr((unsigned*)&s_vm[2 * a2.y + 1], 1u << 5);
            atomicOr((unsigned*)&s_vm[2 * a3.x + 1], 1u << 6);
            atomicOr((unsigned*)&s_vm[2 * a3.y + 1], 1u << 7);
            atomicOr((unsigned*)&s_vm[2 * a4.x + 1], 1u << 8);
            atomicOr((unsigned*)&s_vm[2 * a4.y + 1], 1u << 9);
        }
    }
    __syncthreads();

    // ---- phase 1: masked accumulation (warp = i-stripe; lane halves = h-halves) ----
    {
        const int d  = lane & 15;
        const int hb = (lane >> 4) * 5;       // 0 or 5
        float a0 = 0.f, a1 = 0.f, a2 = 0.f, a3 = 0.f, a4 = 0.f;
#pragma unroll 8
        for (int i = w; i < I_; i += 16) {    // 72 iterations, MLP 8
            float2   vm = *(const float2*)&s_vm[2 * i];
            unsigned m  = __float_as_uint(vm.y) >> hb;
            float    t0 = vm.x * ub[(size_t)i * ROWSTRIDE + d];
            if (m & 1u)  a0 += t0;
            if (m & 2u)  a1 += t0;
            if (m & 4u)  a2 += t0;
            if (m & 8u)  a3 += t0;
            if (m & 16u) a4 += t0;
        }
        atomicAdd(&s_MuNum[(hb + 0) * D_ + d], a0);
        atomicAdd(&s_MuNum[(hb + 1) * D_ + d], a1);
        atomicAdd(&s_MuNum[(hb + 2) * D_ + d], a2);
        atomicAdd(&s_MuNum[(hb + 3) * D_ + d], a3);
        atomicAdd(&s_MuNum[(hb + 4) * D_ + d], a4);
    }

    // ---- phase 1b: den pass (10 warps, one h each) ----
    if (w < H_) {
        unsigned bit = 1u << w;
        float dn = 0.f;
#pragma unroll 4
        for (int i = lane; i < I_; i += 32) {
            float2 vm = *(const float2*)&s_vm[2 * i];
            if (__float_as_uint(vm.y) & bit) dn += vm.x;
        }
#pragma unroll
        for (int off = 16; off > 0; off >>= 1)
            dn += __shfl_down_sync(0xffffffffu, dn, off);
        if (lane == 0) s_den[w] = dn;
    }
    __syncthreads();

    if (tid < H_ * D_) {
        int h = tid >> 4;
        s_Mu[h][tid & 15] = s_MuNum[tid] / s_den[h];
    }
    __syncthreads();
    if (tid < H_) {
        float m2 = 0.f;
#pragma unroll
        for (int dd = 0; dd < D_; dd++) { float x = s_Mu[tid][dd]; m2 += x * x; }
        s_mu2[tid] = m2;
    }
    __syncthreads();

    // ---- phase 2: quad-decomposed losses (u from L2, Mu quarters in regs) ----
    {
        const int dq = tid & 3;               // d-quarter owned
        const int g  = tid >> 2;              // 0..127 (i-group)
#pragma unroll 1
        for (int pass = 0; pass < 2; pass++) {
            const int hb = pass * 5;
            float4 mq[5];
#pragma unroll
            for (int hh = 0; hh < 5; hh++)
                mq[hh] = *(const float4*)(&s_Mu[hb + hh][dq * 4]);
            float l0 = 0.f, l1 = 0.f, l2 = 0.f, l3 = 0.f, l4 = 0.f;
#pragma unroll 1
            for (int k = 0; k < I_ / 128; k++) {  // 9 iterations
                int i = g + k * 128;
                float4 q = *(const float4*)(ub + (size_t)i * ROWSTRIDE + dq * 4);
                float  v = s_vm[2 * i];
                float sq = v * v;
#pragma unroll
                for (int hh = 0; hh < 5; hh++) {
                    float dot = q.x * mq[hh].x + q.y * mq[hh].y
                              + q.z * mq[hh].z + q.w * mq[hh].w;
                    dot += __shfl_xor_sync(0xffffffffu, dot, 1);
                    dot += __shfl_xor_sync(0xffffffffu, dot, 2);
                    float val = sqrt_approx(
                        fmaxf(sq + fmaf(-2.f, dot, s_mu2[hb + hh]), 0.f));
                    if (hh == 0) l0 += val;        // x4 per i, argmin invariant
                    else if (hh == 1) l1 += val;
                    else if (hh == 2) l2 += val;
                    else if (hh == 3) l3 += val;
                    else l4 += val;
                }
            }
#pragma unroll
            for (int off = 16; off > 0; off >>= 1) {
                l0 += __shfl_down_sync(0xffffffffu, l0, off);
                l1 += __shfl_down_sync(0xffffffffu, l1, off);
                l2 += __shfl_down_sync(0xffffffffu, l2, off);
                l3 += __shfl_down_sync(0xffffffffu, l3, off);
                l4 += __shfl_down_sync(0xffffffffu, l4, off);
            }
            if (lane == 0) {
                s_loss[w][hb + 0] = l0;
                s_loss[w][hb + 1] = l1;
                s_loss[w][hb + 2] = l2;
                s_loss[w][hb + 3] = l3;
                s_loss[w][hb + 4] = l4;
            }
        }
    }
    __syncthreads();

    // ---- argmin + output: warp 0 only (shfl min-reduce) ----
    if (w == 0) {
        float myv = 3.4e38f;
        int   myh = 0;
        if (lane < H_) {
            float l = 0.f;
#pragma unroll
            for (int ww = 0; ww < 16; ww++) l += s_loss[ww][lane];
            myv = l; myh = lane;
        }
#pragma unroll
        for (int off = 16; off > 0; off >>= 1) {
            float ov = __shfl_xor_sync(0xffffffffu, myv, off);
            int   oh = __shfl_xor_sync(0xffffffffu, myh, off);
            if (ov < myv || (ov == myv && oh < myh)) { myv = ov; myh = oh; }
        }
        if (lane < D_) out[(size_t)bo * D_ + lane] = s_Mu[myh][lane];
    }
}

// ---------------------------------------------------------------------------
extern "C" void kernel_launch(void* const* d_in, const int* in_sizes, int n_in,
                              void* d_out, int out_size) {
    const float* u   = (const float*)d_in[0];
    const int*   idx = (const int*)d_in[1];
    float*       out = (float*)d_out;
    (void)in_sizes; (void)n_in; (void)out_size;

    fused_kernel<<<B_ * O_, T_>>>(u, idx, out);
}

// round 10
// speedup vs baseline: 1.1644x; 1.1644x over previous
#include <cuda_runtime.h>
#include <cstdint>

#define B_ 32
#define I_ 1152
#define O_ 10
#define D_ 16
#define H_ 10
#define S_ 922
#define T_ 512
#define PAD 20          // s_u row stride: 80B

__device__ __forceinline__ float sqrt_approx(float x) {
    float y;
    asm("sqrt.approx.f32 %0, %1;" : "=f"(y) : "f"(x));
    return y;
}

// ---------------------------------------------------------------------------
// One block per (b,o). u staged in smem (2 blocks/SM).
//  0:  dtype probe (safe), zero, load u -> s_u
//  0b: vn (approx sqrt); vectorized idx gather -> smem atomicOr bitmask
//  1:  masked weighted accumulation -> Mu numerators (5 acc/thread)
//  1b: den pass (10 warps); Mu = num/den; mu2
//  2:  BUTTERFLY loss: per group of 4 h, quad lanes compute 4 partial dots,
//      3-shfl transpose-reduce -> each lane owns full dot of distinct h,
//      exactly 1 sqrt/lane (no quad redundancy). Groups {0-3},{4-7},{8,9}.
//  argmin by warp 0 (shfl reduce), emit Mu[h*]
// ---------------------------------------------------------------------------
__global__ void __launch_bounds__(T_, 2) fused_kernel(const float* __restrict__ u,
                                                      const int* __restrict__ idx,
                                                      float* __restrict__ out) {
    extern __shared__ float sm[];
    float*    s_u    = sm;                         // [1152][PAD]
    float*    s_vn   = sm + I_ * PAD;              // [1152]
    unsigned* s_mask = (unsigned*)(s_vn + I_);     // [1152]

    __shared__ float s_MuNum[H_ * D_];
    __shared__ float s_den[H_];
    __shared__ __align__(16) float s_Mu[H_][D_];
    __shared__ float s_mu2[H_];
    __shared__ float s_loss[16][H_];
    __shared__ int   s_is64;

    const int bo   = blockIdx.x;
    const int b    = bo / O_;
    const int o    = bo % O_;
    const int tid  = threadIdx.x;
    const int lane = tid & 31;
    const int w    = tid >> 5;      // warp 0..15

    const float* ub = u + ((size_t)b * I_ * O_ + o) * D_;

    // ---- phase 0: dtype probe + zero + load u ----
    if (w == 0) {
        unsigned v = ((const unsigned*)idx)[2 * lane + 1]
                   | ((const unsigned*)idx)[2 * (lane + 32) + 1];
        unsigned r = __reduce_or_sync(0xffffffffu, v);
        if (lane == 0) s_is64 = (r == 0u) ? 1 : 0;
    }
    for (int j = tid; j < I_; j += T_) s_mask[j] = 0u;
    if (tid < H_ * D_) s_MuNum[tid] = 0.f;

    for (int e = tid; e < I_ * 4; e += T_) {
        int i = e >> 2, j = e & 3;
        float4 q = *(const float4*)(ub + (size_t)i * (O_ * D_) + j * 4);
        *(float4*)(s_u + i * PAD + j * 4) = q;
    }
    __syncthreads();

    // ---- phase 0b: norms + vectorized gather/scatter ----
    for (int i = tid; i < I_; i += T_) {
        const float4* p = (const float4*)(s_u + i * PAD);
        float4 q0 = p[0], q1 = p[1], q2 = p[2], q3 = p[3];
        float s = q0.x * q0.x + q0.y * q0.y + q0.z * q0.z + q0.w * q0.w
                + q1.x * q1.x + q1.y * q1.y + q1.z * q1.z + q1.w * q1.w
                + q2.x * q2.x + q2.y * q2.y + q2.z * q2.z + q2.w * q2.w
                + q3.x * q3.x + q3.y * q3.y + q3.z * q3.z + q3.w * q3.w;
        s_vn[i] = sqrt_approx(s);
    }

    if (s_is64) {
#pragma unroll 1
        for (int s = tid; s < S_; s += T_) {
            int base = ((b * S_ + s) * O_ + o) * H_;
            const int4* p = (const int4*)idx + (base >> 1);
            int4 a0 = p[0], a1 = p[1], a2 = p[2], a3 = p[3], a4 = p[4];
            atomicOr(&s_mask[a0.x], 1u << 0);
            atomicOr(&s_mask[a0.z], 1u << 1);
            atomicOr(&s_mask[a1.x], 1u << 2);
            atomicOr(&s_mask[a1.z], 1u << 3);
            atomicOr(&s_mask[a2.x], 1u << 4);
            atomicOr(&s_mask[a2.z], 1u << 5);
            atomicOr(&s_mask[a3.x], 1u << 6);
            atomicOr(&s_mask[a3.z], 1u << 7);
            atomicOr(&s_mask[a4.x], 1u << 8);
            atomicOr(&s_mask[a4.z], 1u << 9);
        }
    } else {
#pragma unroll 1
        for (int s = tid; s < S_; s += T_) {
            int base = ((b * S_ + s) * O_ + o) * H_;
            const int2* p = (const int2*)idx + (base >> 1);
            int2 a0 = p[0], a1 = p[1], a2 = p[2], a3 = p[3], a4 = p[4];
            atomicOr(&s_mask[a0.x], 1u << 0);
            atomicOr(&s_mask[a0.y], 1u << 1);
            atomicOr(&s_mask[a1.x], 1u << 2);
            atomicOr(&s_mask[a1.y], 1u << 3);
            atomicOr(&s_mask[a2.x], 1u << 4);
            atomicOr(&s_mask[a2.y], 1u << 5);
            atomicOr(&s_mask[a3.x], 1u << 6);
            atomicOr(&s_mask[a3.y], 1u << 7);
            atomicOr(&s_mask[a4.x], 1u << 8);
            atomicOr(&s_mask[a4.y], 1u << 9);
        }
    }
    __syncthreads();

    // ---- phase 1: masked accumulation (warp = i-stripe; lane halves = h-halves) ----
    {
        const int d  = lane & 15;
        const int hb = (lane >> 4) * 5;       // 0 or 5
        float a0 = 0.f, a1 = 0.f, a2 = 0.f, a3 = 0.f, a4 = 0.f;
#pragma unroll 4
        for (int i = w; i < I_; i += 16) {    // 72 iterations
            unsigned m  = s_mask[i] >> hb;
            float    t0 = s_vn[i] * s_u[i * PAD + d];
            if (m & 1u)  a0 += t0;
            if (m & 2u)  a1 += t0;
            if (m & 4u)  a2 += t0;
            if (m & 8u)  a3 += t0;
            if (m & 16u) a4 += t0;
        }
        atomicAdd(&s_MuNum[(hb + 0) * D_ + d], a0);
        atomicAdd(&s_MuNum[(hb + 1) * D_ + d], a1);
        atomicAdd(&s_MuNum[(hb + 2) * D_ + d], a2);
        atomicAdd(&s_MuNum[(hb + 3) * D_ + d], a3);
        atomicAdd(&s_MuNum[(hb + 4) * D_ + d], a4);
    }

    // ---- phase 1b: den pass (10 warps, one h each) ----
    if (w < H_) {
        unsigned bit = 1u << w;
        float dn = 0.f;
#pragma unroll 4
        for (int i = lane; i < I_; i += 32)
            if (s_mask[i] & bit) dn += s_vn[i];
#pragma unroll
        for (int off = 16; off > 0; off >>= 1)
            dn += __shfl_down_sync(0xffffffffu, dn, off);
        if (lane == 0) s_den[w] = dn;
    }
    __syncthreads();

    if (tid < H_ * D_) {
        int h = tid >> 4;
        s_Mu[h][tid & 15] = s_MuNum[tid] / s_den[h];
    }
    __syncthreads();
    if (tid < H_) {
        float m2 = 0.f;
#pragma unroll
        for (int dd = 0; dd < D_; dd++) { float x = s_Mu[tid][dd]; m2 += x * x; }
        s_mu2[tid] = m2;
    }
    __syncthreads();

    // ---- phase 2: butterfly losses ----
    {
        const int dq   = tid & 3;             // d-quarter owned
        const int g    = tid >> 2;            // 0..127 (i owner)
        const int sel  = lane & 1;
        const int bit1 = (lane >> 1) & 1;

        // groups 0,1: 4 hypotheses each
#pragma unroll 1
        for (int grp = 0; grp < 2; grp++) {
            const int hb = grp * 4;
            float4 mq0 = *(const float4*)(&s_Mu[hb + 0][dq * 4]);
            float4 mq1 = *(const float4*)(&s_Mu[hb + 1][dq * 4]);
            float4 mq2 = *(const float4*)(&s_Mu[hb + 2][dq * 4]);
            float4 mq3 = *(const float4*)(&s_Mu[hb + 3][dq * 4]);
            const float u2 = s_mu2[hb + 2 * bit1 + sel];   // my final h
            float lacc = 0.f;
#pragma unroll 1
            for (int k = 0; k < I_ / 128; k++) {          // 9 iterations
                int i = g + k * 128;
                float4 q = *(const float4*)(s_u + i * PAD + dq * 4);
                float  v = s_vn[i];
                float sq = v * v;
                float p0 = q.x * mq0.x + q.y * mq0.y + q.z * mq0.z + q.w * mq0.w;
                float p1 = q.x * mq1.x + q.y * mq1.y + q.z * mq1.z + q.w * mq1.w;
                float p2 = q.x * mq2.x + q.y * mq2.y + q.z * mq2.z + q.w * mq2.w;
                float p3 = q.x * mq3.x + q.y * mq3.y + q.z * mq3.z + q.w * mq3.w;
                // step 1 (xor 1): pair-combine; I keep h = hb+sel, hb+2+sel
                float keep_lo = sel ? p1 : p0;
                float send_lo = sel ? p0 : p1;
                float C_lo = keep_lo + __shfl_xor_sync(0xffffffffu, send_lo, 1);
                float keep_hi = sel ? p3 : p2;
                float send_hi = sel ? p2 : p3;
                float C_hi = keep_hi + __shfl_xor_sync(0xffffffffu, send_hi, 1);
                // step 2 (xor 2): final h = hb + 2*bit1 + sel
                float keep2 = bit1 ? C_hi : C_lo;
                float send2 = bit1 ? C_lo : C_hi;
                float dot = keep2 + __shfl_xor_sync(0xffffffffu, send2, 2);
                lacc += sqrt_approx(fmaxf(sq + fmaf(-2.f, dot, u2), 0.f));
            }
            // reduce across the 8 quads (offsets preserve lane&3)
            lacc += __shfl_down_sync(0xffffffffu, lacc, 16);
            lacc += __shfl_down_sync(0xffffffffu, lacc, 8);
            lacc += __shfl_down_sync(0xffffffffu, lacc, 4);
            if (lane < 4) s_loss[w][hb + lane] = lacc;    // 2*bit1+sel == lane
        }

        // group 2: h8, h9
        {
            float4 m8 = *(const float4*)(&s_Mu[8][dq * 4]);
            float4 m9 = *(const float4*)(&s_Mu[9][dq * 4]);
            const float u2 = s_mu2[8 + sel];
            float lacc = 0.f;
#pragma unroll 1
            for (int k = 0; k < I_ / 128; k++) {
                int i = g + k * 128;
                float4 q = *(const float4*)(s_u + i * PAD + dq * 4);
                float  v = s_vn[i];
                float sq = v * v;
                float p8 = q.x * m8.x + q.y * m8.y + q.z * m8.z + q.w * m8.w;
                float p9 = q.x * m9.x + q.y * m9.y + q.z * m9.z + q.w * m9.w;
                float keep = sel ? p9 : p8;
                float send = sel ? p8 : p9;
                float C = keep + __shfl_xor_sync(0xffffffffu, send, 1);
                float dot = C + __shfl_xor_sync(0xffffffffu, C, 2);  // full dot, h=8+sel
                lacc += sqrt_approx(fmaxf(sq + fmaf(-2.f, dot, u2), 0.f));
            }
            // columns dq=2,3 duplicate dq=0,1; reduce preserving dq, keep lanes 0,1
            lacc += __shfl_down_sync(0xffffffffu, lacc, 16);
            lacc += __shfl_down_sync(0xffffffffu, lacc, 8);
            lacc += __shfl_down_sync(0xffffffffu, lacc, 4);
            if (lane < 2) s_loss[w][8 + lane] = lacc;
        }
    }
    __syncthreads();

    // ---- argmin + output: warp 0 only (shfl min-reduce) ----
    if (w == 0) {
        float myv = 3.4e38f;
        int   myh = 0;
        if (lane < H_) {
            float l = 0.f;
#pragma unroll
            for (int ww = 0; ww < 16; ww++) l += s_loss[ww][lane];
            myv = l; myh = lane;
        }
#pragma unroll
        for (int off = 16; off > 0; off >>= 1) {
            float ov = __shfl_xor_sync(0xffffffffu, myv, off);
            int   oh = __shfl_xor_sync(0xffffffffu, myh, off);
            if (ov < myv || (ov == myv && oh < myh)) { myv = ov; myh = oh; }
        }
        if (lane < D_) out[(size_t)bo * D_ + lane] = s_Mu[myh][lane];
    }
}

// ---------------------------------------------------------------------------
extern "C" void kernel_launch(void* const* d_in, const int* in_sizes, int n_in,
                              void* d_out, int out_size) {
    const float* u   = (const float*)d_in[0];
    const int*   idx = (const int*)d_in[1];
    float*       out = (float*)d_out;
    (void)in_sizes; (void)n_in; (void)out_size;

    const int dynSmem = (I_ * PAD + I_ + I_) * 4;   // 101376 bytes
    static int attr_set = 0;
    if (!attr_set) {
        cudaFuncSetAttribute(fused_kernel,
                             cudaFuncAttributeMaxDynamicSharedMemorySize, dynSmem);
        attr_set = 1;
    }
    fused_kernel<<<B_ * O_, T_, dynSmem>>>(u, idx, out);
}